// round 16
// baseline (speedup 1.0000x reference)
#include <cuda_runtime.h>
#include <cstdint>

// ---------------------------------------------------------------------------
// minLSTM cell, fused single kernel: grouped linears + gate math + scan.
// R14 = R13 resubmission (broker failed; R7->R9 precedent says resubmit).
// R4 structure (best so far) + instruction diet:
//   - Wf, Wi pre-scaled by -log2(e)  -> ex2 directly, no per-element FMUL
//   - exp(EPS) cumsum factor dropped -> bias <= 8.2e-5 (gate is 1e-3)
//   - sc double-buffered by iteration -> closes latent cross-iter race
//
// Shapes: x (B=4, S=8192, D=1024), W* (128 groups, 8, 8), out (4, 8192, 1024).
//
// Exact algebraic rewrite of the reference:
//   F,I,G = grouped 8x8 linears
//   eF=exp(-F), eI=exp(-I), s = 2+eF+eI
//   f = (1+eI)/s
//   i = (1+eF)/s
//   g = G>=0 ? G+0.5 : sigmoid(G)      (0.5+1e-8 == 0.5 in fp32)
//   h_t = f_t * h_{t-1} + i_t * g_t,   h_{-1} = 0
//
// One CTA owns one (batch, group-quad) chain of 32 channels for all 8192
// timesteps -> no inter-block communication. 16 warps = 16 time slabs per
// 256-t macro-iteration; carry crosses iterations via double-buffered smem
// with one barrier per iteration.
// ---------------------------------------------------------------------------

namespace {
constexpr int kS       = 8192;
constexpr int kD       = 1024;
constexpr int kWarps   = 16;
constexpr int kThreads = kWarps * 32;            // 512
constexpr int kTper    = 16;                     // timesteps per thread
constexpr int kIterT   = kWarps * kTper;         // 256 timesteps per iteration
constexpr int kNIter   = kS / kIterT;            // 32
constexpr int kNChain  = 128;                    // 4 batches * 32 group-quads
constexpr float kNegLog2e = -1.4426950408889634f;
}  // namespace

__device__ float g_wf2[128 * 64];                // Wf * -log2(e)
__device__ float g_wi2[128 * 64];                // Wi * -log2(e)

__global__ void prep_kernel(const float* __restrict__ Wf,
                            const float* __restrict__ Wi) {
  int i = blockIdx.x * blockDim.x + threadIdx.x;
  if (i < 128 * 64) {
    g_wf2[i] = Wf[i] * kNegLog2e;
    g_wi2[i] = Wi[i] * kNegLog2e;
  }
}

__device__ __forceinline__ float ex2f(float x) {
  float r;
  asm("ex2.approx.f32 %0, %1;" : "=f"(r) : "f"(x));
  return r;
}
__device__ __forceinline__ float frcp(float x) {
  float r;
  asm("rcp.approx.f32 %0, %1;" : "=f"(r) : "f"(x));
  return r;
}

__global__ __launch_bounds__(kThreads, 1) void minlstm_kernel(
    const float* __restrict__ x, const float* __restrict__ Wh,
    float* __restrict__ out) {
  const int chain = blockIdx.x;                  // 0..127
  const int b     = chain >> 5;
  const int gq    = chain & 31;                  // group-quad (4 groups, 32 ch)
  const int w     = threadIdx.x >> 5;            // warp = time slab
  const int c     = threadIdx.x & 31;            // lane = channel

  // Per-channel weight rows (8 each); 8 lanes of a group share x inputs.
  const int row = gq * 32 + c;
  const float4 wf0 = *reinterpret_cast<const float4*>(g_wf2 + row * 8);
  const float4 wf1 = *reinterpret_cast<const float4*>(g_wf2 + row * 8 + 4);
  const float4 wi0 = *reinterpret_cast<const float4*>(g_wi2 + row * 8);
  const float4 wi1 = *reinterpret_cast<const float4*>(g_wi2 + row * 8 + 4);
  const float4 wh0 = *reinterpret_cast<const float4*>(Wh + row * 8);
  const float4 wh1 = *reinterpret_cast<const float4*>(Wh + row * 8 + 4);

  __shared__ float2 sc[2][kWarps][32];           // double-buffered aggregates
  __shared__ float  Hs[2][32];                   // double-buffered carry
  if (threadIdx.x < 32) { Hs[0][c] = 0.f; Hs[1][c] = 0.f; }

  const float* xbase = x + (size_t)b * kS * kD + gq * 32 + (c & 24);
  float* obase       = out + (size_t)b * kS * kD + gq * 32 + c;

  for (int iter = 0; iter < kNIter; iter++) {
    const int buf = iter & 1;
    const int t0  = iter * kIterT + w * kTper;
    const float* xp = xbase + (size_t)t0 * kD;

    float aj[kTper], bj[kTper];
    float A = 1.f, Bv = 0.f;                     // running affine for this slab
#pragma unroll
    for (int j = 0; j < kTper; j++) {
      const float4 xa = *reinterpret_cast<const float4*>(xp + (size_t)j * kD);
      const float4 xb = *reinterpret_cast<const float4*>(xp + (size_t)j * kD + 4);

      float Fd = xa.x * wf0.x;                   // pre-scaled by -log2e
      Fd = fmaf(xa.y, wf0.y, Fd); Fd = fmaf(xa.z, wf0.z, Fd); Fd = fmaf(xa.w, wf0.w, Fd);
      Fd = fmaf(xb.x, wf1.x, Fd); Fd = fmaf(xb.y, wf1.y, Fd);
      Fd = fmaf(xb.z, wf1.z, Fd); Fd = fmaf(xb.w, wf1.w, Fd);

      float Id = xa.x * wi0.x;
      Id = fmaf(xa.y, wi0.y, Id); Id = fmaf(xa.z, wi0.z, Id); Id = fmaf(xa.w, wi0.w, Id);
      Id = fmaf(xb.x, wi1.x, Id); Id = fmaf(xb.y, wi1.y, Id);
      Id = fmaf(xb.z, wi1.z, Id); Id = fmaf(xb.w, wi1.w, Id);

      float G = xa.x * wh0.x;
      G = fmaf(xa.y, wh0.y, G); G = fmaf(xa.z, wh0.z, G); G = fmaf(xa.w, wh0.w, G);
      G = fmaf(xb.x, wh1.x, G); G = fmaf(xb.y, wh1.y, G);
      G = fmaf(xb.z, wh1.z, G); G = fmaf(xb.w, wh1.w, G);

      const float eF = ex2f(Fd);                 // e^{-F}
      const float eI = ex2f(Id);                 // e^{-I}
      const float s  = 2.f + eF + eI;
      const float rd = frcp(s);
      const float f  = fmaf(eI, rd, rd);         // (1+eI)/s
      const float ic = fmaf(eF, rd, rd);         // (1+eF)/s
      const float g  = (G >= 0.f) ? (G + 0.5f)
                                  : frcp(1.f + ex2f(G * kNegLog2e));
      const float v  = ic * g;

      aj[j] = f;
      bj[j] = v;
      A *= f;
      Bv = fmaf(f, Bv, v);
    }

    sc[buf][w][c] = make_float2(A, Bv);
    __syncthreads();                             // sc[buf] visible; Hs stable

    // Exclusive prefix over earlier slabs for this channel.
    float Ae = 1.f, Be = 0.f;
    for (int k = 0; k < w; k++) {
      const float2 p = sc[buf][k][c];
      Be = fmaf(p.x, Be, p.y);
      Ae *= p.x;
    }

    const float Hp = Hs[buf][c];                 // carry entering this iteration

    // Last slab publishes next carry into the other buffer (readers sync at
    // the next iteration's __syncthreads()).
    if (w == kWarps - 1) {
      Hs[buf ^ 1][c] = fmaf(A * Ae, Hp, fmaf(A, Be, Bv));
    }

    // Apply carry and emit; lanes are 32 contiguous floats -> coalesced 128B.
    float h = fmaf(Ae, Hp, Be);
    float* op = obase + (size_t)t0 * kD;
#pragma unroll
    for (int j = 0; j < kTper; j++) {
      h = fmaf(aj[j], h, bj[j]);
      op[(size_t)j * kD] = h;
    }
  }
}

extern "C" void kernel_launch(void* const* d_in, const int* in_sizes, int n_in,
                              void* d_out, int out_size) {
  (void)in_sizes; (void)n_in; (void)out_size;
  const float* x  = (const float*)d_in[0];
  const float* Wf = (const float*)d_in[1];
  const float* Wi = (const float*)d_in[2];
  const float* Wh = (const float*)d_in[3];
  float* out = (float*)d_out;

  prep_kernel<<<32, 256>>>(Wf, Wi);
  minlstm_kernel<<<kNChain, kThreads>>>(x, Wh, out);
}

// round 17
// speedup vs baseline: 1.0159x; 1.0159x over previous
#include <cuda_runtime.h>
#include <cstdint>

// ---------------------------------------------------------------------------
// minLSTM cell, fused: grouped linears on TENSOR CORES (tf32 mma.sync) +
// gate math + scan. Dots moved off the FMA pipe; scan stays the proven
// R4 chain-resident serial form via a per-warp smem (f,v) transpose.
//
// Shapes: x (B=4, S=8192, D=1024), W* (128 groups, 8, 8), out (4, 8192, 1024).
//
// Math (algebraic rewrite of the reference):
//   F,I,G = grouped 8x8 linears (F,I computed pre-scaled by -log2e)
//   eF=2^Fd (=e^-F), eI=2^Id, s = 2+eF+eI
//   f = (1+eI)/s,  i = (1+eF)/s
//   g = G>=0 ? G+0.5 : sigmoid(G)
//   h_t = f_t * h_{t-1} + i_t * g_t,  h_{-1} = 0
//
// One CTA per (batch, group-quad) chain of 32 channels; 16 warps = 16 time
// slabs of 16 t; warp-tile = 16t x 32ch done as 4 groups x 3 gates of
// m16n8k8 tf32 MMA. (f,v) transposed through per-warp smem back to
// lane=channel layout; then R4's scan/carry/emit verbatim.
// ---------------------------------------------------------------------------

namespace {
constexpr int kS        = 8192;
constexpr int kD        = 1024;
constexpr int kWarps    = 16;
constexpr int kThreads  = kWarps * 32;           // 512
constexpr int kTileT    = 16;                    // timesteps per warp tile
constexpr int kIterT    = kWarps * kTileT;       // 256 t per iteration
constexpr int kNIter    = kS / kIterT;           // 32
constexpr int kNChain   = 128;                   // 4 batches * 32 group-quads
constexpr int kFvStride = 17;                    // float2 per channel row (pad)
constexpr int kFvPerWarp = 32 * kFvStride;       // float2 count per warp
constexpr float kNegLog2e = -1.4426950408889634f;
}  // namespace

__device__ __forceinline__ float ex2f(float x) {
  float r; asm("ex2.approx.f32 %0, %1;" : "=f"(r) : "f"(x)); return r;
}
__device__ __forceinline__ float frcp(float x) {
  float r; asm("rcp.approx.f32 %0, %1;" : "=f"(r) : "f"(x)); return r;
}
__device__ __forceinline__ uint32_t to_tf32(float x) {
  uint32_t r; asm("cvt.rna.tf32.f32 %0, %1;" : "=r"(r) : "f"(x)); return r;
}
__device__ __forceinline__ void mma8(float* d, const uint32_t* a,
                                     const uint32_t* bb) {
  asm("mma.sync.aligned.m16n8k8.row.col.f32.tf32.tf32.f32 "
      "{%0,%1,%2,%3}, {%4,%5,%6,%7}, {%8,%9}, {%0,%1,%2,%3};"
      : "+f"(d[0]), "+f"(d[1]), "+f"(d[2]), "+f"(d[3])
      : "r"(a[0]), "r"(a[1]), "r"(a[2]), "r"(a[3]), "r"(bb[0]), "r"(bb[1]));
}

__global__ __launch_bounds__(kThreads, 1) void minlstm_kernel(
    const float* __restrict__ x, const float* __restrict__ Wf,
    const float* __restrict__ Wi, const float* __restrict__ Wh,
    float* __restrict__ out) {
  extern __shared__ float2 fv_all[];             // [warp][ch=32][17] float2
  const int chain = blockIdx.x;                  // 0..127
  const int b     = chain >> 5;
  const int gq    = chain & 31;                  // group-quad (4 groups, 32 ch)
  const int w     = threadIdx.x >> 5;            // warp = time slab
  const int c     = threadIdx.x & 31;            // lane
  const int r     = c >> 2;                      // mma groupID (row/quad)
  const int q     = c & 3;                       // mma threadID in group
  float2* fv = fv_all + w * kFvPerWarp;

  // B fragments, once per kernel. B[k][n] = W[n][k]; b0=(k=q,n=r), b1=(k=q+4).
  // Wf, Wi pre-scaled by -log2e so ex2(dot) = e^{-F}.
  uint32_t bf[4][2], bi[4][2], bh[4][2];
#pragma unroll
  for (int m = 0; m < 4; m++) {
    const int oc = (gq * 32 + m * 8 + r) * 8 + q;
    bf[m][0] = to_tf32(Wf[oc] * kNegLog2e);
    bf[m][1] = to_tf32(Wf[oc + 4] * kNegLog2e);
    bi[m][0] = to_tf32(Wi[oc] * kNegLog2e);
    bi[m][1] = to_tf32(Wi[oc + 4] * kNegLog2e);
    bh[m][0] = to_tf32(Wh[oc]);
    bh[m][1] = to_tf32(Wh[oc + 4]);
  }

  __shared__ float2 sc[2][kWarps][32];           // double-buffered aggregates
  __shared__ float  Hs[2][32];                   // double-buffered carry
  if (threadIdx.x < 32) { Hs[0][c] = 0.f; Hs[1][c] = 0.f; }

  const float* xw = x + (size_t)b * kS * kD + gq * 32;
  float* obase    = out + (size_t)b * kS * kD + gq * 32 + c;

  for (int iter = 0; iter < kNIter; iter++) {
    const int buf = iter & 1;
    const int t0  = iter * kIterT + w * kTileT;
    const float* xt = xw + (size_t)t0 * kD;

    // ---- gates via tensor cores: 4 groups x (F, I, G) ----
#pragma unroll
    for (int m = 0; m < 4; m++) {
      const float* xp = xt + m * 8 + q;          // A[row=t, col=k]
      uint32_t a[4];
      a[0] = to_tf32(xp[(size_t)r * kD]);        // (t=r,   k=q)
      a[1] = to_tf32(xp[(size_t)(r + 8) * kD]);  // (t=r+8, k=q)
      a[2] = to_tf32(xp[(size_t)r * kD + 4]);    // (t=r,   k=q+4)
      a[3] = to_tf32(xp[(size_t)(r + 8) * kD + 4]);
      float Df[4] = {0.f, 0.f, 0.f, 0.f};
      float Di[4] = {0.f, 0.f, 0.f, 0.f};
      float Dh[4] = {0.f, 0.f, 0.f, 0.f};
      mma8(Df, a, bf[m]);
      mma8(Di, a, bi[m]);
      mma8(Dh, a, bh[m]);

      // D slot s -> (t = r + (s&2 ? 8:0), ch = m*8 + 2q + (s&1)).
#pragma unroll
      for (int s = 0; s < 4; s++) {
        const float eF = ex2f(Df[s]);            // e^{-F}
        const float eI = ex2f(Di[s]);            // e^{-I}
        const float G  = Dh[s];
        const float sm = 2.f + eF + eI;
        const float rd = frcp(sm);
        const float f  = fmaf(eI, rd, rd);       // (1+eI)/s
        const float ic = fmaf(eF, rd, rd);       // (1+eF)/s
        const float g  = (G >= 0.f) ? (G + 0.5f)
                                    : frcp(1.f + ex2f(G * kNegLog2e));
        const int ch = m * 8 + 2 * q + (s & 1);
        const int tt = r + ((s & 2) ? 8 : 0);
        fv[ch * kFvStride + tt] = make_float2(f, ic * g);
      }
    }
    __syncwarp();                                // transpose visible in-warp

    // ---- R4 scan: lane = channel, serial over 16 t ----
    float aj[kTileT], bj[kTileT];
    float A = 1.f, Bv = 0.f;
#pragma unroll
    for (int j = 0; j < kTileT; j++) {
      const float2 p = fv[c * kFvStride + j];
      aj[j] = p.x;
      bj[j] = p.y;
      A *= p.x;
      Bv = fmaf(p.x, Bv, p.y);
    }

    sc[buf][w][c] = make_float2(A, Bv);
    __syncthreads();                             // sc visible; Hs stable

    float Ae = 1.f, Be = 0.f;
    for (int k = 0; k < w; k++) {
      const float2 p = sc[buf][k][c];
      Be = fmaf(p.x, Be, p.y);
      Ae *= p.x;
    }

    const float Hp = Hs[buf][c];
    if (w == kWarps - 1) {
      Hs[buf ^ 1][c] = fmaf(A * Ae, Hp, fmaf(A, Be, Bv));
    }

    float h = fmaf(Ae, Hp, Be);
    float* op = obase + (size_t)t0 * kD;
#pragma unroll
    for (int j = 0; j < kTileT; j++) {
      h = fmaf(aj[j], h, bj[j]);
      op[(size_t)j * kD] = h;                    // coalesced 128B per t
    }
  }
}

extern "C" void kernel_launch(void* const* d_in, const int* in_sizes, int n_in,
                              void* d_out, int out_size) {
  (void)in_sizes; (void)n_in; (void)out_size;
  const float* x  = (const float*)d_in[0];
  const float* Wf = (const float*)d_in[1];
  const float* Wi = (const float*)d_in[2];
  const float* Wh = (const float*)d_in[3];
  float* out = (float*)d_out;

  const int smem_bytes = kWarps * kFvPerWarp * (int)sizeof(float2);  // 69632
  cudaFuncSetAttribute(minlstm_kernel,
                       cudaFuncAttributeMaxDynamicSharedMemorySize, smem_bytes);
  minlstm_kernel<<<kNChain, kThreads, smem_bytes>>>(x, Wf, Wi, Wh, out);
}